// round 13
// baseline (speedup 1.0000x reference)
#include <cuda_runtime.h>
#include <math.h>

#define BATCH  1024
#define DIM    256
#define TSTEPS 128
#define HID    256
#define NOUT   64
#define JC     80     // j-rows of each hidden matrix cached in smem

__device__ float g_cur1[(size_t)TSTEPS * BATCH * HID];  // [t][b][h]
__device__ float g_WTin[DIM * HID];        // [d][h]
__device__ float g_WTh [HID * HID];        // [j][h]
__device__ float g_WTh1[HID * HID];        // [j][h]
__device__ float g_Wfa [HID * NOUT * 2];   // [j][o][2] (wf, wa)

typedef unsigned long long ull;
typedef unsigned int uint32;

__device__ __forceinline__ void ffma2(ull& acc, ull a, ull b) {
    asm("fma.rn.f32x2 %0, %1, %2, %0;" : "+l"(acc) : "l"(a), "l"(b));
}
__device__ __forceinline__ ull mul2(ull a, ull b) {
    ull r; asm("mul.rn.f32x2 %0, %1, %2;" : "=l"(r) : "l"(a), "l"(b)); return r;
}
__device__ __forceinline__ ull add2(ull a, ull b) {
    ull r; asm("add.rn.f32x2 %0, %1, %2;" : "=l"(r) : "l"(a), "l"(b)); return r;
}
__device__ __forceinline__ ull pack2(float x, float y) {
    ull r; asm("mov.b64 %0, {%1, %2};" : "=l"(r) : "f"(x), "f"(y)); return r;
}
__device__ __forceinline__ ull pack2u(uint32 x, uint32 y) {
    ull r; asm("mov.b64 %0, {%1, %2};" : "=l"(r) : "r"(x), "r"(y)); return r;
}
__device__ __forceinline__ void unpack2(ull v, float& x, float& y) {
    asm("mov.b64 {%0, %1}, %2;" : "=f"(x), "=f"(y) : "l"(v));
}
__device__ __forceinline__ float clamp01(float v) {
    return fminf(fmaxf(v, 0.0f), 1.0f);
}
// bf16 spike constants: 1.0f -> 0x3F80 (exact), 0.0f -> 0x0000.
#define SPIKE1 0x3F80u
// bf16 pair (r0,r1) -> f32x2 (r0,r1): exact for 0.0/1.0 (bits << 16)
__device__ __forceinline__ void spk2(uint32 p, ull& s01) {
    s01 = pack2u(p << 16, p & 0xFFFF0000u);
}

__global__ void dummy_k() {}

// ---------------------------------------------------------------------------
__global__ void prep_weights(const float* __restrict__ W_in,
                             const float* __restrict__ W_h,
                             const float* __restrict__ W_h1,
                             const float* __restrict__ W_f,
                             const float* __restrict__ W_a) {
    if (blockIdx.z == 3) {
        int idx = (blockIdx.y * 8 + blockIdx.x) * 256 + threadIdx.y * 32 + threadIdx.x;
        int j = idx >> 6, oo = idx & 63;
        g_Wfa[idx * 2]     = W_f[oo * HID + j];
        g_Wfa[idx * 2 + 1] = W_a[oo * HID + j];
        return;
    }
    __shared__ float tile[32][33];
    const float* in; float* out;
    switch (blockIdx.z) {
        case 0:  in = W_in; out = g_WTin; break;
        case 1:  in = W_h;  out = g_WTh;  break;
        default: in = W_h1; out = g_WTh1; break;
    }
    int c0 = blockIdx.x * 32, r0 = blockIdx.y * 32;
    int tx = threadIdx.x, ty = threadIdx.y;
    #pragma unroll
    for (int k = 0; k < 32; k += 8)
        tile[ty + k][tx] = in[(r0 + ty + k) * 256 + (c0 + tx)];
    __syncthreads();
    #pragma unroll
    for (int k = 0; k < 32; k += 8)
        out[(c0 + ty + k) * 256 + (r0 + tx)] = tile[tx][ty + k];
}

// ---------------------------------------------------------------------------
// cur1[t][b][h] = sum_d x[b][d][t]*W_in[h][d].  (unchanged — bit-exact)
// ---------------------------------------------------------------------------
__global__ void __launch_bounds__(512) precompute_cur1(const float* __restrict__ x) {
    extern __shared__ __align__(16) float xS[];
    ull* xsu = reinterpret_cast<ull*>(xS);
    const int tid = threadIdx.x;
    const int t0  = blockIdx.x * 64;
    const int b   = blockIdx.y;

    {
        int d = tid >> 1, th = (tid & 1) * 32;
        const float4* xp = reinterpret_cast<const float4*>(
            x + ((size_t)b * DIM + d) * TSTEPS + t0 + th);
        #pragma unroll
        for (int q = 0; q < 8; ++q) {
            float4 v = __ldg(xp + q);
            xsu[d * 32 + th / 2 + 2 * q]     = pack2(v.x, v.y);
            xsu[d * 32 + th / 2 + 2 * q + 1] = pack2(v.z, v.w);
        }
    }
    __syncthreads();

    const int hp = tid & 127;
    const int tg = tid >> 7;
    ull acc[16];
    #pragma unroll
    for (int i = 0; i < 16; ++i) acc[i] = 0ull;

    const ull* gw = reinterpret_cast<const ull*>(g_WTin) + hp;
    #pragma unroll 1
    for (int blk = 0; blk < 32; ++blk) {
        ull wv[8];
        #pragma unroll
        for (int i = 0; i < 8; ++i)
            wv[i] = __ldg(gw + (blk * 8 + i) * 128);
        #pragma unroll
        for (int i = 0; i < 8; ++i) {
            const int j = blk * 8 + i;
            float w0, w1; unpack2(wv[i], w0, w1);
            ull wa = pack2(w0, w0), wb = pack2(w1, w1);
            const ull* xr = xsu + j * 32 + tg * 8;
            #pragma unroll
            for (int tp = 0; tp < 8; ++tp) {
                ull xv = xr[tp];
                ffma2(acc[tp],     xv, wa);
                ffma2(acc[8 + tp], xv, wb);
            }
        }
    }
    #pragma unroll
    for (int tp = 0; tp < 8; ++tp) {
        float a0, a1, b0, b1;
        unpack2(acc[tp], a0, a1);
        unpack2(acc[8 + tp], b0, b1);
        int t = t0 + tg * 16 + 2 * tp;
        *reinterpret_cast<ull*>(g_cur1 + ((size_t)t * BATCH + b) * HID + 2 * hp)
            = pack2(a0, b0);
        *reinterpret_cast<ull*>(g_cur1 + ((size_t)(t + 1) * BATCH + b) * HID + 2 * hp)
            = pack2(a1, b1);
    }
}

// ---------------------------------------------------------------------------
// Uncached-j helpers: blocks of 8, register double-buffered. 8-row version.
// ---------------------------------------------------------------------------
__device__ __forceinline__ void ld8(ull* buf, const ull* gb, int blk) {
    #pragma unroll
    for (int i = 0; i < 8; ++i)
        buf[i] = __ldg(gb + (JC + blk * 8 + i) * 128);
}
__device__ __forceinline__ void use8(const ull* buf, const char* sIn,
                                     int blk, ull* acc) {
    #pragma unroll
    for (int i = 0; i < 8; ++i) {
        const int j = JC + blk * 8 + i;
        float w0, w1; unpack2(buf[i], w0, w1);
        ull wa = pack2(w0, w0), wb = pack2(w1, w1);
        uint4 sv = *reinterpret_cast<const uint4*>(sIn + j * 16);
        ull s01, s23, s45, s67;
        spk2(sv.x, s01); spk2(sv.y, s23);
        spk2(sv.z, s45); spk2(sv.w, s67);
        ffma2(acc[0], s01, wa); ffma2(acc[1], s23, wa);
        ffma2(acc[2], s45, wa); ffma2(acc[3], s67, wa);
        ffma2(acc[4], s01, wb); ffma2(acc[5], s23, wb);
        ffma2(acc[6], s45, wb); ffma2(acc[7], s67, wb);
    }
}

// ---------------------------------------------------------------------------
// Hidden layer: thread owns 2 h x 8 rows. Chains serial over j — bit-exact.
// ---------------------------------------------------------------------------
__device__ __forceinline__ void layer8r(
    const float* sW, const ull* __restrict__ gWp, const char* sIn, int hp,
    float bias0, float bias1, float bc0, float bc1, float thr0, float thr1,
    float* m /*16: [hh*8+r]*/, char* sOut)
{
    ull acc[8];
    #pragma unroll
    for (int i = 0; i < 8; ++i) acc[i] = 0ull;
    const ull* sWp = reinterpret_cast<const ull*>(sW) + hp;
    #pragma unroll 4
    for (int j = 0; j < JC; ++j) {
        ull w = sWp[j * 128];
        float w0, w1; unpack2(w, w0, w1);
        ull wa = pack2(w0, w0), wb = pack2(w1, w1);
        uint4 sv = *reinterpret_cast<const uint4*>(sIn + j * 16);
        ull s01, s23, s45, s67;
        spk2(sv.x, s01); spk2(sv.y, s23);
        spk2(sv.z, s45); spk2(sv.w, s67);
        ffma2(acc[0], s01, wa); ffma2(acc[1], s23, wa);
        ffma2(acc[2], s45, wa); ffma2(acc[3], s67, wa);
        ffma2(acc[4], s01, wb); ffma2(acc[5], s23, wb);
        ffma2(acc[6], s45, wb); ffma2(acc[7], s67, wb);
    }
    // 176 uncached rows = 22 blocks of 8, register double-buffered
    const ull* gb = gWp + hp;
    ull A8[8], B8[8];
    ld8(A8, gb, 0);
    #pragma unroll 1
    for (int i = 0; i < 10; ++i) {
        ld8(B8, gb, 2 * i + 1);
        use8(A8, sIn, 2 * i, acc);
        ld8(A8, gb, 2 * i + 2);
        use8(B8, sIn, 2 * i + 1, acc);
    }
    ld8(B8, gb, 21);
    use8(A8, sIn, 20, acc);
    use8(B8, sIn, 21, acc);

    #pragma unroll
    for (int hh = 0; hh < 2; ++hh) {
        float bias = hh ? bias1 : bias0;
        float bc   = hh ? bc1 : bc0;
        float thr  = hh ? thr1 : thr0;
        uint32 wds[4];
        #pragma unroll
        for (int p = 0; p < 4; ++p) {
            float c0, c1; unpack2(acc[hh * 4 + p], c0, c1);
            float* mm = m + hh * 8 + 2 * p;
            float ca = __fadd_rn(c0, bias);
            float cb = __fadd_rn(c1, bias);
            float ra = (mm[0] > thr) ? thr : 0.0f;     // reset from PREV mem
            float rb = (mm[1] > thr) ? thr : 0.0f;
            float na = __fsub_rn(__fadd_rn(__fmul_rn(bc, mm[0]), ca), ra);
            float nb = __fsub_rn(__fadd_rn(__fmul_rn(bc, mm[1]), cb), rb);
            mm[0] = na; mm[1] = nb;
            uint32 sa = (na > thr) ? SPIKE1 : 0u;
            uint32 sb = (nb > thr) ? SPIKE1 : 0u;
            wds[p] = sa | (sb << 16);
        }
        ulonglong2 v;
        v.x = pack2u(wds[0], wds[1]);
        v.y = pack2u(wds[2], wds[3]);
        *reinterpret_cast<ulonglong2*>(sOut + (2 * hp + hh) * 16) = v;
    }
}

// ---------------------------------------------------------------------------
// Recurrent kernel: 128 CTAs x 384 threads.
//  A (warps 0-3, 128t): hp = tid, 2 h x 8 rows. bf16 spikes, 4-warp coverage
//    halves spike/weight re-read phases vs 8-warp layouts.
//  B (warps 4-11, 256t): output-LI GEMM for step k-1 (identical to R11 path)
// smem: sWh 80KB | sWh1 80KB | spike bufs 4x4KB | scr 16KB = 192KB
// ---------------------------------------------------------------------------
#define SMEM_BYTES (2 * JC * HID * 4 + 4 * 4096 + 16384)

__global__ void __launch_bounds__(384, 1) snn_rec(
    const float* __restrict__ b_in,  const float* __restrict__ beta1,
    const float* __restrict__ thr1,
    const float* __restrict__ b_h,   const float* __restrict__ beta2,
    const float* __restrict__ thr2,
    const float* __restrict__ b_h1,
    const float* __restrict__ b_f,   const float* __restrict__ beta_f,
    const float* __restrict__ b_a,   const float* __restrict__ beta_a,
    float* __restrict__ out)
{
    extern __shared__ __align__(16) char dsmc[];
    float* sWh  = reinterpret_cast<float*>(dsmc);
    float* sWh1 = sWh + JC * HID;
    char*  s1P  = reinterpret_cast<char*>(sWh1 + JC * HID);   // 4096B each
    char*  s2P  = s1P + 4096;
    char*  s3a  = s2P + 4096;
    char*  s3b  = s3a + 4096;
    ull*   scr  = reinterpret_cast<ull*>(s3b + 4096);         // 16KB

    const int tid = threadIdx.x;
    const int b0  = blockIdx.x * 8;

    for (int i = tid; i < JC * HID; i += 384) {
        sWh[i]  = g_WTh[i];
        sWh1[i] = g_WTh1[i];
    }

    if (tid < 128) {
        // ===================== A role: 2h x 8 rows =====================
        const int hp = tid;
        const int h0 = 2 * hp, h1 = h0 + 1;
        const float bin0 = b_in[h0],  bin1 = b_in[h1];
        const float b1c0 = clamp01(beta1[h0]), b1c1 = clamp01(beta1[h1]);
        const float t10 = thr1[h0],  t11 = thr1[h1];
        const float bh0 = b_h[h0],   bh1 = b_h[h1];
        const float b2c0 = clamp01(beta2[h0]), b2c1 = clamp01(beta2[h1]);
        const float t20 = thr2[h0],  t21 = thr2[h1];
        const float bh10 = b_h1[h0], bh11 = b_h1[h1];

        float m1[16], m2[16], m3[16];
        #pragma unroll
        for (int i = 0; i < 16; ++i) { m1[i] = 0.f; m2[i] = 0.f; m3[i] = 0.f; }

        ull c1p[8];   // per row: (h0,h1)
        #pragma unroll
        for (int r = 0; r < 8; ++r)
            c1p[r] = __ldg(reinterpret_cast<const ull*>(
                g_cur1 + ((size_t)0 * BATCH + b0 + r) * HID + h0));

        __syncthreads();   // weight caches ready

        const ull* gWh  = reinterpret_cast<const ull*>(g_WTh);
        const ull* gWh1 = reinterpret_cast<const ull*>(g_WTh1);

        for (int k = 0; k <= TSTEPS; ++k) {
            if (k < TSTEPS) {
                // ---- LIF layer 1: 2h x 8 rows -> bf16 spikes ----
                uint32 wh0[4], wh1[4];
                #pragma unroll
                for (int p = 0; p < 4; ++p) {
                    float ca0, ca1, cb0, cb1;
                    unpack2(c1p[2 * p],     ca0, ca1);   // row 2p:   (h0, h1)
                    unpack2(c1p[2 * p + 1], cb0, cb1);   // row 2p+1: (h0, h1)
                    // h0
                    float x0 = __fadd_rn(ca0, bin0);
                    float x1 = __fadd_rn(cb0, bin0);
                    float r0 = (m1[2 * p] > t10) ? t10 : 0.0f;
                    float r1 = (m1[2 * p + 1] > t10) ? t10 : 0.0f;
                    float n0 = __fsub_rn(__fadd_rn(__fmul_rn(b1c0, m1[2 * p]), x0), r0);
                    float n1 = __fsub_rn(__fadd_rn(__fmul_rn(b1c0, m1[2 * p + 1]), x1), r1);
                    m1[2 * p] = n0; m1[2 * p + 1] = n1;
                    wh0[p] = ((n0 > t10) ? SPIKE1 : 0u) | (((n1 > t10) ? SPIKE1 : 0u) << 16);
                    // h1
                    float y0 = __fadd_rn(ca1, bin1);
                    float y1 = __fadd_rn(cb1, bin1);
                    float s0 = (m1[8 + 2 * p] > t11) ? t11 : 0.0f;
                    float s1 = (m1[8 + 2 * p + 1] > t11) ? t11 : 0.0f;
                    float q0 = __fsub_rn(__fadd_rn(__fmul_rn(b1c1, m1[8 + 2 * p]), y0), s0);
                    float q1 = __fsub_rn(__fadd_rn(__fmul_rn(b1c1, m1[8 + 2 * p + 1]), y1), s1);
                    m1[8 + 2 * p] = q0; m1[8 + 2 * p + 1] = q1;
                    wh1[p] = ((q0 > t11) ? SPIKE1 : 0u) | (((q1 > t11) ? SPIKE1 : 0u) << 16);
                }
                {
                    ulonglong2 v;
                    v.x = pack2u(wh0[0], wh0[1]); v.y = pack2u(wh0[2], wh0[3]);
                    *reinterpret_cast<ulonglong2*>(s1P + h0 * 16) = v;
                    v.x = pack2u(wh1[0], wh1[1]); v.y = pack2u(wh1[2], wh1[3]);
                    *reinterpret_cast<ulonglong2*>(s1P + h1 * 16) = v;
                }
                if (k + 1 < TSTEPS) {
                    #pragma unroll
                    for (int r = 0; r < 8; ++r)
                        c1p[r] = __ldg(reinterpret_cast<const ull*>(
                            g_cur1 + ((size_t)(k + 1) * BATCH + b0 + r) * HID + h0));
                }
                asm volatile("bar.sync 1, 128;" ::: "memory");

                layer8r(sWh, gWh, s1P, hp,
                        bh0, bh1, b2c0, b2c1, t20, t21, m2, s2P);
                asm volatile("bar.sync 1, 128;" ::: "memory");

                char* s3 = (k & 1) ? s3b : s3a;
                layer8r(sWh1, gWh1, s2P, hp,
                        bh10, bh11, b2c0, b2c1, t20, t21, m3, s3);  // bug preserved
            }
            __syncthreads();   // publish s3(k) to B
        }
    } else {
        // ===================== B role (identical to R11) =====================
        const int bt = tid - 128;
        const int o  = bt & 63;
        const int q  = bt >> 6;
        const ull bias_fa = pack2(b_f[o], b_a[o]);
        const ull beta_fa = pack2(clamp01(beta_f[o]), clamp01(beta_a[o]));
        ull macc0 = pack2(0.f, 0.f), macc1 = macc0;
        const ull* wrow = reinterpret_cast<const ull*>(g_Wfa);

        __syncthreads();

        for (int k = 0; k <= TSTEPS; ++k) {
            if (k >= 1) {
                const char* s3 = ((k - 1) & 1) ? s3b : s3a;
                ull accF[4] = {0ull, 0ull, 0ull, 0ull};
                ull accA[4] = {0ull, 0ull, 0ull, 0ull};
                const int j0 = q * 64;
                #pragma unroll 8
                for (int jj = 0; jj < 64; ++jj) {
                    int j = j0 + jj;
                    ull wv = __ldg(wrow + j * 64 + o);
                    float wf, wa; unpack2(wv, wf, wa);
                    ull wf2 = pack2(wf, wf), wa2 = pack2(wa, wa);
                    uint4 sv = *reinterpret_cast<const uint4*>(s3 + j * 16);
                    ull s01, s23, s45, s67;
                    spk2(sv.x, s01); spk2(sv.y, s23);
                    spk2(sv.z, s45); spk2(sv.w, s67);
                    ffma2(accF[0], s01, wf2); ffma2(accF[1], s23, wf2);
                    ffma2(accF[2], s45, wf2); ffma2(accF[3], s67, wf2);
                    ffma2(accA[0], s01, wa2); ffma2(accA[1], s23, wa2);
                    ffma2(accA[2], s45, wa2); ffma2(accA[3], s67, wa2);
                }
                #pragma unroll
                for (int r2 = 0; r2 < 4; ++r2) {
                    scr[r2 * 256 + q * 64 + o]        = accF[r2];
                    scr[1024 + r2 * 256 + q * 64 + o] = accA[r2];
                }
                asm volatile("bar.sync 2, 256;" ::: "memory");
                ull Fs = pack2(0.f, 0.f), As = Fs;
                #pragma unroll
                for (int qq = 0; qq < 4; ++qq) {
                    Fs = add2(Fs, scr[q * 256 + qq * 64 + o]);
                    As = add2(As, scr[1024 + q * 256 + qq * 64 + o]);
                }
                float f0, f1, a0, a1;
                unpack2(Fs, f0, f1);
                unpack2(As, a0, a1);
                macc0 = add2(mul2(beta_fa, macc0), add2(pack2(f0, a0), bias_fa));
                macc1 = add2(mul2(beta_fa, macc1), add2(pack2(f1, a1), bias_fa));
            }
            __syncthreads();
        }

        float mf0, ma0, mf1, ma1;
        unpack2(macc0, mf0, ma0);
        unpack2(macc1, mf1, ma1);
        int row = b0 + 2 * q;
        out[(size_t)row * NOUT + o]                              = 1.0f / (1.0f + expf(-mf0));
        out[(size_t)(row + 1) * NOUT + o]                        = 1.0f / (1.0f + expf(-mf1));
        out[(size_t)BATCH * NOUT + (size_t)row * NOUT + o]       = 1.0f / (1.0f + expf(-ma0));
        out[(size_t)BATCH * NOUT + (size_t)(row + 1) * NOUT + o] = 1.0f / (1.0f + expf(-ma1));
    }
}

// ---------------------------------------------------------------------------
extern "C" void kernel_launch(void* const* d_in, const int* in_sizes, int n_in,
                              void* d_out, int out_size) {
    const float* x      = (const float*)d_in[0];
    const float* W_in   = (const float*)d_in[1];
    const float* b_in   = (const float*)d_in[2];
    const float* beta1  = (const float*)d_in[3];
    const float* thr1   = (const float*)d_in[4];
    const float* W_h    = (const float*)d_in[5];
    const float* b_h    = (const float*)d_in[6];
    const float* beta2  = (const float*)d_in[7];
    const float* thr2   = (const float*)d_in[8];
    const float* W_h1   = (const float*)d_in[9];
    const float* b_h1   = (const float*)d_in[10];
    const float* W_f    = (const float*)d_in[11];
    const float* b_f    = (const float*)d_in[12];
    const float* beta_f = (const float*)d_in[13];
    const float* W_a    = (const float*)d_in[14];
    const float* b_a    = (const float*)d_in[15];
    const float* beta_a = (const float*)d_in[16];
    float* out = (float*)d_out;

    cudaFuncSetAttribute(snn_rec, cudaFuncAttributeMaxDynamicSharedMemorySize,
                         SMEM_BYTES);
    cudaFuncSetAttribute(precompute_cur1,
                         cudaFuncAttributeMaxDynamicSharedMemorySize, 65536);

    dummy_k<<<1, 1>>>();
    prep_weights<<<dim3(8, 8, 4), dim3(32, 8)>>>(W_in, W_h, W_h1, W_f, W_a);
    precompute_cur1<<<dim3(2, BATCH), 512, 65536>>>(x);
    snn_rec<<<BATCH / 8, 384, SMEM_BYTES>>>(b_in, beta1, thr1, b_h, beta2, thr2,
                                            b_h1, b_f, beta_f, b_a, beta_a, out);
}

// round 14
// speedup vs baseline: 1.1153x; 1.1153x over previous
#include <cuda_runtime.h>
#include <math.h>

#define BATCH  1024
#define DIM    256
#define TSTEPS 128
#define HID    256
#define NOUT   64
#define JC     80

__device__ float g_cur1[(size_t)TSTEPS * BATCH * HID];
__device__ float g_WTin[DIM * HID];
__device__ float g_WTh [HID * HID];
__device__ float g_WTh1[HID * HID];
__device__ float g_Wfa [HID * NOUT * 2];

typedef unsigned long long ull;
typedef unsigned int uint32;

__device__ __forceinline__ void ffma2(ull& acc, ull a, ull b) {
    asm("fma.rn.f32x2 %0, %1, %2, %0;" : "+l"(acc) : "l"(a), "l"(b));
}
__device__ __forceinline__ ull mul2(ull a, ull b) {
    ull r; asm("mul.rn.f32x2 %0, %1, %2;" : "=l"(r) : "l"(a), "l"(b)); return r;
}
__device__ __forceinline__ ull add2(ull a, ull b) {
    ull r; asm("add.rn.f32x2 %0, %1, %2;" : "=l"(r) : "l"(a), "l"(b)); return r;
}
__device__ __forceinline__ ull pack2(float x, float y) {
    ull r; asm("mov.b64 %0, {%1, %2};" : "=l"(r) : "f"(x), "f"(y)); return r;
}
__device__ __forceinline__ ull pack2u(uint32 x, uint32 y) {
    ull r; asm("mov.b64 %0, {%1, %2};" : "=l"(r) : "r"(x), "r"(y)); return r;
}
__device__ __forceinline__ void unpack2(ull v, float& x, float& y) {
    asm("mov.b64 {%0, %1}, %2;" : "=f"(x), "=f"(y) : "l"(v));
}
__device__ __forceinline__ float clamp01(float v) {
    return fminf(fmaxf(v, 0.0f), 1.0f);
}
#define SPIKE1 0x3F80u
__device__ __forceinline__ void spk2(uint32 p, ull& s01) {
    s01 = pack2u(p << 16, p & 0xFFFF0000u);
}

__global__ void dummy_k() {}

// ---------------------------------------------------------------------------
__global__ void prep_weights(const float* __restrict__ W_in,
                             const float* __restrict__ W_h,
                             const float* __restrict__ W_h1,
                             const float* __restrict__ W_f,
                             const float* __restrict__ W_a) {
    if (blockIdx.z == 3) {
        int idx = (blockIdx.y * 8 + blockIdx.x) * 256 + threadIdx.y * 32 + threadIdx.x;
        int j = idx >> 6, oo = idx & 63;
        g_Wfa[idx * 2]     = W_f[oo * HID + j];
        g_Wfa[idx * 2 + 1] = W_a[oo * HID + j];
        return;
    }
    __shared__ float tile[32][33];
    const float* in; float* out;
    switch (blockIdx.z) {
        case 0:  in = W_in; out = g_WTin; break;
        case 1:  in = W_h;  out = g_WTh;  break;
        default: in = W_h1; out = g_WTh1; break;
    }
    int c0 = blockIdx.x * 32, r0 = blockIdx.y * 32;
    int tx = threadIdx.x, ty = threadIdx.y;
    #pragma unroll
    for (int k = 0; k < 32; k += 8)
        tile[ty + k][tx] = in[(r0 + ty + k) * 256 + (c0 + tx)];
    __syncthreads();
    #pragma unroll
    for (int k = 0; k < 32; k += 8)
        out[(c0 + ty + k) * 256 + (r0 + tx)] = tile[tx][ty + k];
}

// ---------------------------------------------------------------------------
__global__ void __launch_bounds__(512) precompute_cur1(const float* __restrict__ x) {
    extern __shared__ __align__(16) float xS[];
    ull* xsu = reinterpret_cast<ull*>(xS);
    const int tid = threadIdx.x;
    const int t0  = blockIdx.x * 64;
    const int b   = blockIdx.y;
    {
        int d = tid >> 1, th = (tid & 1) * 32;
        const float4* xp = reinterpret_cast<const float4*>(
            x + ((size_t)b * DIM + d) * TSTEPS + t0 + th);
        #pragma unroll
        for (int q = 0; q < 8; ++q) {
            float4 v = __ldg(xp + q);
            xsu[d * 32 + th / 2 + 2 * q]     = pack2(v.x, v.y);
            xsu[d * 32 + th / 2 + 2 * q + 1] = pack2(v.z, v.w);
        }
    }
    __syncthreads();
    const int hp = tid & 127;
    const int tg = tid >> 7;
    ull acc[16];
    #pragma unroll
    for (int i = 0; i < 16; ++i) acc[i] = 0ull;
    const ull* gw = reinterpret_cast<const ull*>(g_WTin) + hp;
    #pragma unroll 1
    for (int blk = 0; blk < 32; ++blk) {
        ull wv[8];
        #pragma unroll
        for (int i = 0; i < 8; ++i)
            wv[i] = __ldg(gw + (blk * 8 + i) * 128);
        #pragma unroll
        for (int i = 0; i < 8; ++i) {
            const int j = blk * 8 + i;
            float w0, w1; unpack2(wv[i], w0, w1);
            ull wa = pack2(w0, w0), wb = pack2(w1, w1);
            const ull* xr = xsu + j * 32 + tg * 8;
            #pragma unroll
            for (int tp = 0; tp < 8; ++tp) {
                ull xv = xr[tp];
                ffma2(acc[tp],     xv, wa);
                ffma2(acc[8 + tp], xv, wb);
            }
        }
    }
    #pragma unroll
    for (int tp = 0; tp < 8; ++tp) {
        float a0, a1, b0, b1;
        unpack2(acc[tp], a0, a1);
        unpack2(acc[8 + tp], b0, b1);
        int t = t0 + tg * 16 + 2 * tp;
        *reinterpret_cast<ull*>(g_cur1 + ((size_t)t * BATCH + b) * HID + 2 * hp)
            = pack2(a0, b0);
        *reinterpret_cast<ull*>(g_cur1 + ((size_t)(t + 1) * BATCH + b) * HID + 2 * hp)
            = pack2(a1, b1);
    }
}

// ---------------------------------------------------------------------------
// 16-j weight block helpers (2h x 4rows, bf16 spikes)
// ---------------------------------------------------------------------------
__device__ __forceinline__ void ld16(ull* buf, const ull* gb, int blk) {
    #pragma unroll
    for (int i = 0; i < 16; ++i)
        buf[i] = __ldg(gb + (JC + blk * 16 + i) * 128);
}
__device__ __forceinline__ void use16(const ull* buf, const char* sInr,
                                      int blk, ull* acc) {
    #pragma unroll
    for (int i = 0; i < 16; ++i) {
        const int j = JC + blk * 16 + i;
        float w0, w1; unpack2(buf[i], w0, w1);
        ull wa = pack2(w0, w0), wb = pack2(w1, w1);
        uint2 sv = *reinterpret_cast<const uint2*>(sInr + j * 16);
        ull s01, s23;
        spk2(sv.x, s01); spk2(sv.y, s23);
        ffma2(acc[0], s01, wa); ffma2(acc[1], s23, wa);
        ffma2(acc[2], s01, wb); ffma2(acc[3], s23, wb);
    }
}

// One hidden layer, 2h x 4rows, smem JC + uncached ping-pong with bufA
// preloaded (blk0) at entry and re-preloaded (blk0) at exit. Bit-exact.
__device__ __forceinline__ void layerP(
    const float* sW, const ull* gb, const char* sIn, int rg, int hp,
    float bias0, float bias1, float bc0, float bc1, float thr0, float thr1,
    float* m, char* sOut, ull* bufA, ull* bufB)
{
    ull acc[4] = {0ull, 0ull, 0ull, 0ull};
    const char* sInr = sIn + rg * 8;
    const ull* sWp = reinterpret_cast<const ull*>(sW) + hp;
    #pragma unroll 8
    for (int j = 0; j < JC; ++j) {
        float w0, w1; unpack2(sWp[j * 128], w0, w1);
        ull wa = pack2(w0, w0), wb = pack2(w1, w1);
        uint2 sv = *reinterpret_cast<const uint2*>(sInr + j * 16);
        ull s01, s23;
        spk2(sv.x, s01); spk2(sv.y, s23);
        ffma2(acc[0], s01, wa); ffma2(acc[1], s23, wa);
        ffma2(acc[2], s01, wb); ffma2(acc[3], s23, wb);
    }
    #pragma unroll
    for (int i = 0; i < 5; ++i) {
        ld16(bufB, gb, 2 * i + 1);
        use16(bufA, sInr, 2 * i, acc);
        ld16(bufA, gb, 2 * i + 2);
        use16(bufB, sInr, 2 * i + 1, acc);
    }
    use16(bufA, sInr, 10, acc);
    ld16(bufA, gb, 0);                 // prefetch next step's blk0

    #pragma unroll
    for (int hh = 0; hh < 2; ++hh) {
        float bias = hh ? bias1 : bias0;
        float bc   = hh ? bc1 : bc0;
        float thr  = hh ? thr1 : thr0;
        uint32 w01 = 0, w23 = 0;
        #pragma unroll
        for (int p = 0; p < 2; ++p) {
            float c0, c1; unpack2(acc[hh * 2 + p], c0, c1);
            float* mm = m + hh * 4 + 2 * p;
            float ca = __fadd_rn(c0, bias);
            float cb = __fadd_rn(c1, bias);
            float ra = (mm[0] > thr) ? thr : 0.0f;
            float rb = (mm[1] > thr) ? thr : 0.0f;
            float na = __fsub_rn(__fadd_rn(__fmul_rn(bc, mm[0]), ca), ra);
            float nb = __fsub_rn(__fadd_rn(__fmul_rn(bc, mm[1]), cb), rb);
            mm[0] = na; mm[1] = nb;
            uint32 sa = (na > thr) ? SPIKE1 : 0u;
            uint32 sb = (nb > thr) ? SPIKE1 : 0u;
            if (p == 0) w01 = sa | (sb << 16);
            else        w23 = sa | (sb << 16);
        }
        *reinterpret_cast<ull*>(sOut + (2 * hp + hh) * 16 + rg * 8) =
            pack2u(w01, w23);
    }
}

// ---------------------------------------------------------------------------
// Recurrent kernel: 128 CTAs x 512 threads, 2-stage warp pipeline.
//  A (warps 0-7):  LIF1(k) -> s1; L2(k): s1 -> s2[k&1]
//  B (warps 8-15): L3(k-1): s2[(k-1)&1] -> s3[(k-1)&1]; output(k-2)
// smem: sWh 80K | sWh1 80K | s1 4K | s2 x2 | s3 x2 (4K ea) | scr 16K = 196K
// ---------------------------------------------------------------------------
#define SMEM_BYTES (2 * JC * HID * 4 + 5 * 4096 + 16384)

__global__ void __launch_bounds__(512, 1) snn_rec(
    const float* __restrict__ b_in,  const float* __restrict__ beta1,
    const float* __restrict__ thr1,
    const float* __restrict__ b_h,   const float* __restrict__ beta2,
    const float* __restrict__ thr2,
    const float* __restrict__ b_h1,
    const float* __restrict__ b_f,   const float* __restrict__ beta_f,
    const float* __restrict__ b_a,   const float* __restrict__ beta_a,
    float* __restrict__ out)
{
    extern __shared__ __align__(16) char dsmc[];
    float* sWh  = reinterpret_cast<float*>(dsmc);
    float* sWh1 = sWh + JC * HID;
    char*  s1P  = reinterpret_cast<char*>(sWh1 + JC * HID);
    char*  s2a  = s1P + 4096;
    char*  s2b  = s2a + 4096;
    char*  s3a  = s2b + 4096;
    char*  s3b  = s3a + 4096;
    ull*   scr  = reinterpret_cast<ull*>(s3b + 4096);

    const int tid = threadIdx.x;
    const int b0  = blockIdx.x * 8;

    for (int i = tid; i < JC * HID; i += 512) {
        sWh[i]  = g_WTh[i];
        sWh1[i] = g_WTh1[i];
    }

    if (tid < 256) {
        // ============== A: LIF1 + L2 ==============
        const int w    = tid >> 5;
        const int lane = tid & 31;
        const int hp   = w * 16 + (lane >> 1);
        const int rg   = lane & 1;
        const int h0 = 2 * hp, h1 = h0 + 1;
        const float bin0 = b_in[h0],  bin1 = b_in[h1];
        const float b1c0 = clamp01(beta1[h0]), b1c1 = clamp01(beta1[h1]);
        const float t10 = thr1[h0],  t11 = thr1[h1];
        const float bh0 = b_h[h0],   bh1 = b_h[h1];
        const float b2c0 = clamp01(beta2[h0]), b2c1 = clamp01(beta2[h1]);
        const float t20 = thr2[h0],  t21 = thr2[h1];

        float m1[8], m2[8];
        #pragma unroll
        for (int i = 0; i < 8; ++i) { m1[i] = 0.f; m2[i] = 0.f; }

        const int rowbase = b0 + rg * 4;
        ull c1p[4];
        #pragma unroll
        for (int r = 0; r < 4; ++r)
            c1p[r] = __ldg(reinterpret_cast<const ull*>(
                g_cur1 + ((size_t)0 * BATCH + rowbase + r) * HID + h0));

        const ull* gb = reinterpret_cast<const ull*>(g_WTh) + hp;
        ull bufA[16], bufB[16];
        ld16(bufA, gb, 0);

        __syncthreads();

        for (int k = 0; k < TSTEPS + 2; ++k) {
            if (k < TSTEPS) {
                // LIF1 -> s1
                uint32 u0[2], u1[2];
                #pragma unroll
                for (int p = 0; p < 2; ++p) {
                    float ca0, ca1, cb0, cb1;
                    unpack2(c1p[2 * p],     ca0, ca1);
                    unpack2(c1p[2 * p + 1], cb0, cb1);
                    float x0 = __fadd_rn(ca0, bin0);
                    float x1 = __fadd_rn(cb0, bin0);
                    float r0 = (m1[2 * p] > t10) ? t10 : 0.0f;
                    float r1 = (m1[2 * p + 1] > t10) ? t10 : 0.0f;
                    float n0 = __fsub_rn(__fadd_rn(__fmul_rn(b1c0, m1[2 * p]), x0), r0);
                    float n1 = __fsub_rn(__fadd_rn(__fmul_rn(b1c0, m1[2 * p + 1]), x1), r1);
                    m1[2 * p] = n0; m1[2 * p + 1] = n1;
                    u0[p] = ((n0 > t10) ? SPIKE1 : 0u) | (((n1 > t10) ? SPIKE1 : 0u) << 16);
                    float y0 = __fadd_rn(ca1, bin1);
                    float y1 = __fadd_rn(cb1, bin1);
                    float s0 = (m1[4 + 2 * p] > t11) ? t11 : 0.0f;
                    float s1v = (m1[4 + 2 * p + 1] > t11) ? t11 : 0.0f;
                    float q0 = __fsub_rn(__fadd_rn(__fmul_rn(b1c1, m1[4 + 2 * p]), y0), s0);
                    float q1 = __fsub_rn(__fadd_rn(__fmul_rn(b1c1, m1[4 + 2 * p + 1]), y1), s1v);
                    m1[4 + 2 * p] = q0; m1[4 + 2 * p + 1] = q1;
                    u1[p] = ((q0 > t11) ? SPIKE1 : 0u) | (((q1 > t11) ? SPIKE1 : 0u) << 16);
                }
                *reinterpret_cast<ull*>(s1P + h0 * 16 + rg * 8) = pack2u(u0[0], u0[1]);
                *reinterpret_cast<ull*>(s1P + h1 * 16 + rg * 8) = pack2u(u1[0], u1[1]);

                if (k + 1 < TSTEPS) {
                    #pragma unroll
                    for (int r = 0; r < 4; ++r)
                        c1p[r] = __ldg(reinterpret_cast<const ull*>(
                            g_cur1 + ((size_t)(k + 1) * BATCH + rowbase + r) * HID + h0));
                }
                asm volatile("bar.sync 1, 256;" ::: "memory");

                char* s2 = (k & 1) ? s2b : s2a;
                layerP(sWh, gb, s1P, rg, hp,
                       bh0, bh1, b2c0, b2c1, t20, t21, m2, s2, bufA, bufB);
            }
            __syncthreads();
        }
    } else {
        // ============== B: L3(k-1) + output(k-2) ==============
        const int bt   = tid - 256;
        const int w    = bt >> 5;
        const int lane = bt & 31;
        const int hp   = w * 16 + (lane >> 1);
        const int rg   = lane & 1;
        const int h0 = 2 * hp, h1 = h0 + 1;
        const float bh10 = b_h1[h0], bh11 = b_h1[h1];
        const float b2c0 = clamp01(beta2[h0]), b2c1 = clamp01(beta2[h1]);
        const float t20 = thr2[h0],  t21 = thr2[h1];   // bug preserved

        const int o = bt & 63;
        const int q = bt >> 6;
        const ull bias_fa = pack2(b_f[o], b_a[o]);
        const ull beta_fa = pack2(clamp01(beta_f[o]), clamp01(beta_a[o]));
        ull macc0 = pack2(0.f, 0.f), macc1 = macc0;
        const ull* wrow = reinterpret_cast<const ull*>(g_Wfa);

        float m3[8];
        #pragma unroll
        for (int i = 0; i < 8; ++i) m3[i] = 0.f;

        const ull* gb = reinterpret_cast<const ull*>(g_WTh1) + hp;
        ull bufA[16], bufB[16];
        ld16(bufA, gb, 0);

        __syncthreads();

        for (int k = 0; k < TSTEPS + 2; ++k) {
            if (k >= 1 && k <= TSTEPS) {
                const char* s2 = ((k - 1) & 1) ? s2b : s2a;
                char* s3 = ((k - 1) & 1) ? s3b : s3a;
                layerP(sWh1, gb, s2, rg, hp,
                       bh10, bh11, b2c0, b2c1, t20, t21, m3, s3, bufA, bufB);
            }
            if (k >= 2) {
                const char* s3 = ((k - 2) & 1) ? s3b : s3a;
                ull accF[4] = {0ull, 0ull, 0ull, 0ull};
                ull accA[4] = {0ull, 0ull, 0ull, 0ull};
                const int j0 = q * 64;
                #pragma unroll 8
                for (int jj = 0; jj < 64; ++jj) {
                    int j = j0 + jj;
                    ull wv = __ldg(wrow + j * 64 + o);
                    float wf, wa; unpack2(wv, wf, wa);
                    ull wf2 = pack2(wf, wf), wa2 = pack2(wa, wa);
                    uint4 sv = *reinterpret_cast<const uint4*>(s3 + j * 16);
                    ull s01, s23, s45, s67;
                    spk2(sv.x, s01); spk2(sv.y, s23);
                    spk2(sv.z, s45); spk2(sv.w, s67);
                    ffma2(accF[0], s01, wf2); ffma2(accF[1], s23, wf2);
                    ffma2(accF[2], s45, wf2); ffma2(accF[3], s67, wf2);
                    ffma2(accA[0], s01, wa2); ffma2(accA[1], s23, wa2);
                    ffma2(accA[2], s45, wa2); ffma2(accA[3], s67, wa2);
                }
                #pragma unroll
                for (int r2 = 0; r2 < 4; ++r2) {
                    scr[r2 * 256 + q * 64 + o]        = accF[r2];
                    scr[1024 + r2 * 256 + q * 64 + o] = accA[r2];
                }
                asm volatile("bar.sync 2, 256;" ::: "memory");
                ull Fs = pack2(0.f, 0.f), As = Fs;
                #pragma unroll
                for (int qq = 0; qq < 4; ++qq) {
                    Fs = add2(Fs, scr[q * 256 + qq * 64 + o]);
                    As = add2(As, scr[1024 + q * 256 + qq * 64 + o]);
                }
                float f0, f1, a0, a1;
                unpack2(Fs, f0, f1);
                unpack2(As, a0, a1);
                macc0 = add2(mul2(beta_fa, macc0), add2(pack2(f0, a0), bias_fa));
                macc1 = add2(mul2(beta_fa, macc1), add2(pack2(f1, a1), bias_fa));
            }
            __syncthreads();
        }

        float mf0, ma0, mf1, ma1;
        unpack2(macc0, mf0, ma0);
        unpack2(macc1, mf1, ma1);
        int row = b0 + 2 * q;
        out[(size_t)row * NOUT + o]                              = 1.0f / (1.0f + expf(-mf0));
        out[(size_t)(row + 1) * NOUT + o]                        = 1.0f / (1.0f + expf(-mf1));
        out[(size_t)BATCH * NOUT + (size_t)row * NOUT + o]       = 1.0f / (1.0f + expf(-ma0));
        out[(size_t)BATCH * NOUT + (size_t)(row + 1) * NOUT + o] = 1.0f / (1.0f + expf(-ma1));
    }
}

// ---------------------------------------------------------------------------
extern "C" void kernel_launch(void* const* d_in, const int* in_sizes, int n_in,
                              void* d_out, int out_size) {
    const float* x      = (const float*)d_in[0];
    const float* W_in   = (const float*)d_in[1];
    const float* b_in   = (const float*)d_in[2];
    const float* beta1  = (const float*)d_in[3];
    const float* thr1   = (const float*)d_in[4];
    const float* W_h    = (const float*)d_in[5];
    const float* b_h    = (const float*)d_in[6];
    const float* beta2  = (const float*)d_in[7];
    const float* thr2   = (const float*)d_in[8];
    const float* W_h1   = (const float*)d_in[9];
    const float* b_h1   = (const float*)d_in[10];
    const float* W_f    = (const float*)d_in[11];
    const float* b_f    = (const float*)d_in[12];
    const float* beta_f = (const float*)d_in[13];
    const float* W_a    = (const float*)d_in[14];
    const float* b_a    = (const float*)d_in[15];
    const float* beta_a = (const float*)d_in[16];
    float* out = (float*)d_out;

    cudaFuncSetAttribute(snn_rec, cudaFuncAttributeMaxDynamicSharedMemorySize,
                         SMEM_BYTES);
    cudaFuncSetAttribute(precompute_cur1,
                         cudaFuncAttributeMaxDynamicSharedMemorySize, 65536);

    dummy_k<<<1, 1>>>();
    prep_weights<<<dim3(8, 8, 4), dim3(32, 8)>>>(W_in, W_h, W_h1, W_f, W_a);
    precompute_cur1<<<dim3(2, BATCH), 512, 65536>>>(x);
    snn_rec<<<BATCH / 8, 512, SMEM_BYTES>>>(b_in, beta1, thr1, b_h, beta2, thr2,
                                            b_h1, b_f, beta_f, b_a, beta_a, out);
}

// round 15
// speedup vs baseline: 1.1632x; 1.0430x over previous
#include <cuda_runtime.h>
#include <math.h>

#define BATCH  1024
#define DIM    256
#define TSTEPS 128
#define HID    256
#define NOUT   64
#define JC     80

__device__ float g_cur1[(size_t)TSTEPS * BATCH * HID];
__device__ float g_WTin[DIM * HID];
__device__ float g_WTh [HID * HID];
__device__ float g_WTh1[HID * HID];
__device__ float g_Wfa [HID * NOUT * 2];

typedef unsigned long long ull;
typedef unsigned int uint32;

__device__ __forceinline__ void ffma2(ull& acc, ull a, ull b) {
    asm("fma.rn.f32x2 %0, %1, %2, %0;" : "+l"(acc) : "l"(a), "l"(b));
}
__device__ __forceinline__ ull mul2(ull a, ull b) {
    ull r; asm("mul.rn.f32x2 %0, %1, %2;" : "=l"(r) : "l"(a), "l"(b)); return r;
}
__device__ __forceinline__ ull add2(ull a, ull b) {
    ull r; asm("add.rn.f32x2 %0, %1, %2;" : "=l"(r) : "l"(a), "l"(b)); return r;
}
__device__ __forceinline__ ull pack2(float x, float y) {
    ull r; asm("mov.b64 %0, {%1, %2};" : "=l"(r) : "f"(x), "f"(y)); return r;
}
__device__ __forceinline__ ull pack2u(uint32 x, uint32 y) {
    ull r; asm("mov.b64 %0, {%1, %2};" : "=l"(r) : "r"(x), "r"(y)); return r;
}
__device__ __forceinline__ void unpack2(ull v, float& x, float& y) {
    asm("mov.b64 {%0, %1}, %2;" : "=f"(x), "=f"(y) : "l"(v));
}
__device__ __forceinline__ float clamp01(float v) {
    return fminf(fmaxf(v, 0.0f), 1.0f);
}
#define SPIKE1 0x3F80u
// bf16 spike word p = s_even | (s_odd<<16); splats -> f32x2 (s,s), exact 0/1
__device__ __forceinline__ ull splat_lo(uint32 p) {
    uint32 v = p << 16;          return pack2u(v, v);
}
__device__ __forceinline__ ull splat_hi(uint32 p) {
    uint32 v = p & 0xFFFF0000u;  return pack2u(v, v);
}

__global__ void dummy_k() {}

// ---------------------------------------------------------------------------
__global__ void prep_weights(const float* __restrict__ W_in,
                             const float* __restrict__ W_h,
                             const float* __restrict__ W_h1,
                             const float* __restrict__ W_f,
                             const float* __restrict__ W_a) {
    if (blockIdx.z == 3) {
        int idx = (blockIdx.y * 8 + blockIdx.x) * 256 + threadIdx.y * 32 + threadIdx.x;
        int j = idx >> 6, oo = idx & 63;
        g_Wfa[idx * 2]     = W_f[oo * HID + j];
        g_Wfa[idx * 2 + 1] = W_a[oo * HID + j];
        return;
    }
    __shared__ float tile[32][33];
    const float* in; float* out;
    switch (blockIdx.z) {
        case 0:  in = W_in; out = g_WTin; break;
        case 1:  in = W_h;  out = g_WTh;  break;
        default: in = W_h1; out = g_WTh1; break;
    }
    int c0 = blockIdx.x * 32, r0 = blockIdx.y * 32;
    int tx = threadIdx.x, ty = threadIdx.y;
    #pragma unroll
    for (int k = 0; k < 32; k += 8)
        tile[ty + k][tx] = in[(r0 + ty + k) * 256 + (c0 + tx)];
    __syncthreads();
    #pragma unroll
    for (int k = 0; k < 32; k += 8)
        out[(c0 + ty + k) * 256 + (r0 + tx)] = tile[tx][ty + k];
}

// ---------------------------------------------------------------------------
__global__ void __launch_bounds__(512) precompute_cur1(const float* __restrict__ x) {
    extern __shared__ __align__(16) float xS[];
    ull* xsu = reinterpret_cast<ull*>(xS);
    const int tid = threadIdx.x;
    const int t0  = blockIdx.x * 64;
    const int b   = blockIdx.y;
    {
        int d = tid >> 1, th = (tid & 1) * 32;
        const float4* xp = reinterpret_cast<const float4*>(
            x + ((size_t)b * DIM + d) * TSTEPS + t0 + th);
        #pragma unroll
        for (int q = 0; q < 8; ++q) {
            float4 v = __ldg(xp + q);
            xsu[d * 32 + th / 2 + 2 * q]     = pack2(v.x, v.y);
            xsu[d * 32 + th / 2 + 2 * q + 1] = pack2(v.z, v.w);
        }
    }
    __syncthreads();
    const int hp = tid & 127;
    const int tg = tid >> 7;
    ull acc[16];
    #pragma unroll
    for (int i = 0; i < 16; ++i) acc[i] = 0ull;
    const ull* gw = reinterpret_cast<const ull*>(g_WTin) + hp;
    #pragma unroll 1
    for (int blk = 0; blk < 32; ++blk) {
        ull wv[8];
        #pragma unroll
        for (int i = 0; i < 8; ++i)
            wv[i] = __ldg(gw + (blk * 8 + i) * 128);
        #pragma unroll
        for (int i = 0; i < 8; ++i) {
            const int j = blk * 8 + i;
            float w0, w1; unpack2(wv[i], w0, w1);
            ull wa = pack2(w0, w0), wb = pack2(w1, w1);
            const ull* xr = xsu + j * 32 + tg * 8;
            #pragma unroll
            for (int tp = 0; tp < 8; ++tp) {
                ull xv = xr[tp];
                ffma2(acc[tp],     xv, wa);
                ffma2(acc[8 + tp], xv, wb);
            }
        }
    }
    #pragma unroll
    for (int tp = 0; tp < 8; ++tp) {
        float a0, a1, b0, b1;
        unpack2(acc[tp], a0, a1);
        unpack2(acc[8 + tp], b0, b1);
        int t = t0 + tg * 16 + 2 * tp;
        *reinterpret_cast<ull*>(g_cur1 + ((size_t)t * BATCH + b) * HID + 2 * hp)
            = pack2(a0, b0);
        *reinterpret_cast<ull*>(g_cur1 + ((size_t)(t + 1) * BATCH + b) * HID + 2 * hp)
            = pack2(a1, b1);
    }
}

// ---------------------------------------------------------------------------
// Splat-form inner helpers: acc[r] = (h0,h1) f32x2 per local row r.
// ---------------------------------------------------------------------------
__device__ __forceinline__ void ld16(ull* buf, const ull* gb, int blk) {
    #pragma unroll
    for (int i = 0; i < 16; ++i)
        buf[i] = __ldg(gb + (JC + blk * 16 + i) * 128);
}
__device__ __forceinline__ void use16(const ull* buf, const char* sInr,
                                      int blk, ull* acc) {
    #pragma unroll
    for (int i = 0; i < 16; ++i) {
        const int j = JC + blk * 16 + i;
        ull w = buf[i];                               // (w_h0, w_h1) raw
        uint2 sv = *reinterpret_cast<const uint2*>(sInr + j * 16);
        ffma2(acc[0], splat_lo(sv.x), w);
        ffma2(acc[1], splat_hi(sv.x), w);
        ffma2(acc[2], splat_lo(sv.y), w);
        ffma2(acc[3], splat_hi(sv.y), w);
    }
}

// One hidden layer, 2h x 4rows (lanes = h-pair). Per-scalar chains bit-exact.
__device__ __forceinline__ void layerP(
    const float* sW, const ull* gb, const char* sIn, int rg, int hp,
    float bias0, float bias1, float bc0, float bc1, float thr0, float thr1,
    float* m /*[0..3]=h0 rows, [4..7]=h1 rows*/, char* sOut,
    ull* bufA, ull* bufB)
{
    ull acc[4] = {0ull, 0ull, 0ull, 0ull};
    const char* sInr = sIn + rg * 8;
    const ull* sWp = reinterpret_cast<const ull*>(sW) + hp;
    #pragma unroll 8
    for (int j = 0; j < JC; ++j) {
        ull w = sWp[j * 128];
        uint2 sv = *reinterpret_cast<const uint2*>(sInr + j * 16);
        ffma2(acc[0], splat_lo(sv.x), w);
        ffma2(acc[1], splat_hi(sv.x), w);
        ffma2(acc[2], splat_lo(sv.y), w);
        ffma2(acc[3], splat_hi(sv.y), w);
    }
    #pragma unroll
    for (int i = 0; i < 5; ++i) {
        ld16(bufB, gb, 2 * i + 1);
        use16(bufA, sInr, 2 * i, acc);
        ld16(bufA, gb, 2 * i + 2);
        use16(bufB, sInr, 2 * i + 1, acc);
    }
    use16(bufA, sInr, 10, acc);
    ld16(bufA, gb, 0);                 // prefetch next step's blk0

    uint32 h0w[2], h1w[2];
    #pragma unroll
    for (int p = 0; p < 4; ++p) {
        float c0, c1; unpack2(acc[p], c0, c1);     // (h0, h1) for row p
        float ca = __fadd_rn(c0, bias0);
        float r0 = (m[p] > thr0) ? thr0 : 0.0f;
        float n0 = __fsub_rn(__fadd_rn(__fmul_rn(bc0, m[p]), ca), r0);
        m[p] = n0;
        uint32 s0 = (n0 > thr0) ? SPIKE1 : 0u;
        float cb = __fadd_rn(c1, bias1);
        float r1 = (m[4 + p] > thr1) ? thr1 : 0.0f;
        float n1 = __fsub_rn(__fadd_rn(__fmul_rn(bc1, m[4 + p]), cb), r1);
        m[4 + p] = n1;
        uint32 s1 = (n1 > thr1) ? SPIKE1 : 0u;
        if (p & 1) { h0w[p >> 1] |= s0 << 16; h1w[p >> 1] |= s1 << 16; }
        else       { h0w[p >> 1]  = s0;       h1w[p >> 1]  = s1; }
    }
    *reinterpret_cast<ull*>(sOut + (2 * hp) * 16 + rg * 8)     = pack2u(h0w[0], h0w[1]);
    *reinterpret_cast<ull*>(sOut + (2 * hp + 1) * 16 + rg * 8) = pack2u(h1w[0], h1w[1]);
}

// ---------------------------------------------------------------------------
// Recurrent kernel: 128 CTAs x 512 threads, 2-stage warp pipeline.
//  A (warps 0-7):  LIF1(k) -> s1; L2(k): s1 -> s2[k&1]
//  B (warps 8-15): L3(k-1): s2 -> s3[(k-1)&1]; output(k-2) splat-form
// ---------------------------------------------------------------------------
#define SMEM_BYTES (2 * JC * HID * 4 + 5 * 4096 + 16384)

__global__ void __launch_bounds__(512, 1) snn_rec(
    const float* __restrict__ b_in,  const float* __restrict__ beta1,
    const float* __restrict__ thr1,
    const float* __restrict__ b_h,   const float* __restrict__ beta2,
    const float* __restrict__ thr2,
    const float* __restrict__ b_h1,
    const float* __restrict__ b_f,   const float* __restrict__ beta_f,
    const float* __restrict__ b_a,   const float* __restrict__ beta_a,
    float* __restrict__ out)
{
    extern __shared__ __align__(16) char dsmc[];
    float* sWh  = reinterpret_cast<float*>(dsmc);
    float* sWh1 = sWh + JC * HID;
    char*  s1P  = reinterpret_cast<char*>(sWh1 + JC * HID);
    char*  s2a  = s1P + 4096;
    char*  s2b  = s2a + 4096;
    char*  s3a  = s2b + 4096;
    char*  s3b  = s3a + 4096;
    ull*   scr  = reinterpret_cast<ull*>(s3b + 4096);   // 2048 ull = 16KB

    const int tid = threadIdx.x;
    const int b0  = blockIdx.x * 8;

    for (int i = tid; i < JC * HID; i += 512) {
        sWh[i]  = g_WTh[i];
        sWh1[i] = g_WTh1[i];
    }

    if (tid < 256) {
        // ============== A: LIF1 + L2 ==============
        const int w    = tid >> 5;
        const int lane = tid & 31;
        const int hp   = w * 16 + (lane >> 1);
        const int rg   = lane & 1;
        const int h0 = 2 * hp, h1 = h0 + 1;
        const float bin0 = b_in[h0],  bin1 = b_in[h1];
        const float b1c0 = clamp01(beta1[h0]), b1c1 = clamp01(beta1[h1]);
        const float t10 = thr1[h0],  t11 = thr1[h1];
        const float bh0 = b_h[h0],   bh1 = b_h[h1];
        const float b2c0 = clamp01(beta2[h0]), b2c1 = clamp01(beta2[h1]);
        const float t20 = thr2[h0],  t21 = thr2[h1];

        float m1[8], m2[8];
        #pragma unroll
        for (int i = 0; i < 8; ++i) { m1[i] = 0.f; m2[i] = 0.f; }

        const int rowbase = b0 + rg * 4;
        ull c1p[4];
        #pragma unroll
        for (int r = 0; r < 4; ++r)
            c1p[r] = __ldg(reinterpret_cast<const ull*>(
                g_cur1 + ((size_t)0 * BATCH + rowbase + r) * HID + h0));

        const ull* gb = reinterpret_cast<const ull*>(g_WTh) + hp;
        ull bufA[16], bufB[16];
        ld16(bufA, gb, 0);

        __syncthreads();

        for (int k = 0; k < TSTEPS + 2; ++k) {
            if (k < TSTEPS) {
                // LIF1 -> s1  (m1[0..3]=h0 rows, m1[4..7]=h1 rows)
                uint32 h0w[2], h1w[2];
                #pragma unroll
                for (int p = 0; p < 4; ++p) {
                    float c0, c1; unpack2(c1p[p], c0, c1);   // row p: (h0,h1)
                    float ca = __fadd_rn(c0, bin0);
                    float r0 = (m1[p] > t10) ? t10 : 0.0f;
                    float n0 = __fsub_rn(__fadd_rn(__fmul_rn(b1c0, m1[p]), ca), r0);
                    m1[p] = n0;
                    uint32 s0 = (n0 > t10) ? SPIKE1 : 0u;
                    float cb = __fadd_rn(c1, bin1);
                    float r1 = (m1[4 + p] > t11) ? t11 : 0.0f;
                    float n1 = __fsub_rn(__fadd_rn(__fmul_rn(b1c1, m1[4 + p]), cb), r1);
                    m1[4 + p] = n1;
                    uint32 s1v = (n1 > t11) ? SPIKE1 : 0u;
                    if (p & 1) { h0w[p >> 1] |= s0 << 16; h1w[p >> 1] |= s1v << 16; }
                    else       { h0w[p >> 1]  = s0;       h1w[p >> 1]  = s1v; }
                }
                *reinterpret_cast<ull*>(s1P + h0 * 16 + rg * 8) = pack2u(h0w[0], h0w[1]);
                *reinterpret_cast<ull*>(s1P + h1 * 16 + rg * 8) = pack2u(h1w[0], h1w[1]);

                if (k + 1 < TSTEPS) {
                    #pragma unroll
                    for (int r = 0; r < 4; ++r)
                        c1p[r] = __ldg(reinterpret_cast<const ull*>(
                            g_cur1 + ((size_t)(k + 1) * BATCH + rowbase + r) * HID + h0));
                }
                asm volatile("bar.sync 1, 256;" ::: "memory");

                char* s2 = (k & 1) ? s2b : s2a;
                layerP(sWh, gb, s1P, rg, hp,
                       bh0, bh1, b2c0, b2c1, t20, t21, m2, s2, bufA, bufB);
            }
            __syncthreads();
        }
    } else {
        // ============== B: L3(k-1) + output(k-2) ==============
        const int bt   = tid - 256;
        const int w    = bt >> 5;
        const int lane = bt & 31;
        const int hp   = w * 16 + (lane >> 1);
        const int rg   = lane & 1;
        const int h0 = 2 * hp, h1 = h0 + 1;
        const float bh10 = b_h1[h0], bh11 = b_h1[h1];
        const float b2c0 = clamp01(beta2[h0]), b2c1 = clamp01(beta2[h1]);
        const float t20 = thr2[h0],  t21 = thr2[h1];   // bug preserved

        const int o = bt & 63;
        const int q = bt >> 6;
        const ull bias_fa = pack2(b_f[o], b_a[o]);
        const ull beta_fa = pack2(clamp01(beta_f[o]), clamp01(beta_a[o]));
        ull macc0 = pack2(0.f, 0.f), macc1 = macc0;
        const ull* wrow = reinterpret_cast<const ull*>(g_Wfa);

        float m3[8];
        #pragma unroll
        for (int i = 0; i < 8; ++i) m3[i] = 0.f;

        const ull* gb = reinterpret_cast<const ull*>(g_WTh1) + hp;
        ull bufA[16], bufB[16];
        ld16(bufA, gb, 0);

        __syncthreads();

        for (int k = 0; k < TSTEPS + 2; ++k) {
            if (k >= 1 && k <= TSTEPS) {
                const char* s2 = ((k - 1) & 1) ? s2b : s2a;
                char* s3 = ((k - 1) & 1) ? s3b : s3a;
                layerP(sWh1, gb, s2, rg, hp,
                       bh10, bh11, b2c0, b2c1, t20, t21, m3, s3, bufA, bufB);
            }
            if (k >= 2) {
                const char* s3 = ((k - 2) & 1) ? s3b : s3a;
                ull accFA[8];
                #pragma unroll
                for (int i = 0; i < 8; ++i) accFA[i] = 0ull;
                const int j0 = q * 64;
                #pragma unroll 8
                for (int jj = 0; jj < 64; ++jj) {
                    int j = j0 + jj;
                    ull wv = __ldg(wrow + j * 64 + o);     // (wf, wa) raw
                    uint4 sv = *reinterpret_cast<const uint4*>(s3 + j * 16);
                    ffma2(accFA[0], splat_lo(sv.x), wv);
                    ffma2(accFA[1], splat_hi(sv.x), wv);
                    ffma2(accFA[2], splat_lo(sv.y), wv);
                    ffma2(accFA[3], splat_hi(sv.y), wv);
                    ffma2(accFA[4], splat_lo(sv.z), wv);
                    ffma2(accFA[5], splat_hi(sv.z), wv);
                    ffma2(accFA[6], splat_lo(sv.w), wv);
                    ffma2(accFA[7], splat_hi(sv.w), wv);
                }
                #pragma unroll
                for (int r = 0; r < 8; ++r)
                    scr[r * 256 + q * 64 + o] = accFA[r];
                asm volatile("bar.sync 2, 256;" ::: "memory");
                ull S0 = pack2(0.f, 0.f), S1 = S0;
                #pragma unroll
                for (int qq = 0; qq < 4; ++qq)
                    S0 = add2(S0, scr[(2 * q) * 256 + qq * 64 + o]);
                #pragma unroll
                for (int qq = 0; qq < 4; ++qq)
                    S1 = add2(S1, scr[(2 * q + 1) * 256 + qq * 64 + o]);
                macc0 = add2(mul2(beta_fa, macc0), add2(S0, bias_fa));
                macc1 = add2(mul2(beta_fa, macc1), add2(S1, bias_fa));
            }
            __syncthreads();
        }

        float mf0, ma0, mf1, ma1;
        unpack2(macc0, mf0, ma0);
        unpack2(macc1, mf1, ma1);
        int row = b0 + 2 * q;
        out[(size_t)row * NOUT + o]                              = 1.0f / (1.0f + expf(-mf0));
        out[(size_t)(row + 1) * NOUT + o]                        = 1.0f / (1.0f + expf(-mf1));
        out[(size_t)BATCH * NOUT + (size_t)row * NOUT + o]       = 1.0f / (1.0f + expf(-ma0));
        out[(size_t)BATCH * NOUT + (size_t)(row + 1) * NOUT + o] = 1.0f / (1.0f + expf(-ma1));
    }
}

// ---------------------------------------------------------------------------
extern "C" void kernel_launch(void* const* d_in, const int* in_sizes, int n_in,
                              void* d_out, int out_size) {
    const float* x      = (const float*)d_in[0];
    const float* W_in   = (const float*)d_in[1];
    const float* b_in   = (const float*)d_in[2];
    const float* beta1  = (const float*)d_in[3];
    const float* thr1   = (const float*)d_in[4];
    const float* W_h    = (const float*)d_in[5];
    const float* b_h    = (const float*)d_in[6];
    const float* beta2  = (const float*)d_in[7];
    const float* thr2   = (const float*)d_in[8];
    const float* W_h1   = (const float*)d_in[9];
    const float* b_h1   = (const float*)d_in[10];
    const float* W_f    = (const float*)d_in[11];
    const float* b_f    = (const float*)d_in[12];
    const float* beta_f = (const float*)d_in[13];
    const float* W_a    = (const float*)d_in[14];
    const float* b_a    = (const float*)d_in[15];
    const float* beta_a = (const float*)d_in[16];
    float* out = (float*)d_out;

    cudaFuncSetAttribute(snn_rec, cudaFuncAttributeMaxDynamicSharedMemorySize,
                         SMEM_BYTES);
    cudaFuncSetAttribute(precompute_cur1,
                         cudaFuncAttributeMaxDynamicSharedMemorySize, 65536);

    dummy_k<<<1, 1>>>();
    prep_weights<<<dim3(8, 8, 4), dim3(32, 8)>>>(W_in, W_h, W_h1, W_f, W_a);
    precompute_cur1<<<dim3(2, BATCH), 512, 65536>>>(x);
    snn_rec<<<BATCH / 8, 512, SMEM_BYTES>>>(b_in, beta1, thr1, b_h, beta2, thr2,
                                            b_h1, b_f, beta_f, b_a, beta_a, out);
}